// round 13
// baseline (speedup 1.0000x reference)
#include <cuda_runtime.h>
#include <cuda_bf16.h>
#include <cuda_fp16.h>
#include <cstdint>

#define N_NODES 100000
#define N_EDGES 1600000
#define HID 128
#define NBLK ((N_NODES + 255) / 256)     // 391
#define N_TILES ((N_NODES + 127) / 128)  // 782

// ---------------- scratch ----------------------------------------------------
__device__ __align__(16) __half2 g_h16[(size_t)N_NODES * 64]; // xts in fp16
// layer-1 hidden, bf16 hi/lo in MMA-fragment order: [tile][slab][mb][1024 u32]
__device__ __align__(16) uint32_t g_fhi[(size_t)N_TILES * 8192];
__device__ __align__(16) uint32_t g_flo[(size_t)N_TILES * 8192];
__device__ float g_dinv[N_NODES];
__device__ int   g_deg[N_NODES];
__device__ int   g_cur[N_NODES];
__device__ int   g_off[N_NODES];
__device__ int   g_src[N_EDGES];
__device__ int   g_total;
__device__ int   g_is64;

// ---------------- helpers ----------------------------------------------------
__device__ __forceinline__ uint32_t smem_u32(const void* p) {
    uint32_t a;
    asm("{ .reg .u64 t; cvta.to.shared.u64 t, %1; cvt.u32.u64 %0, t; }"
        : "=r"(a) : "l"(p));
    return a;
}
__device__ __forceinline__ void cp_async16(uint32_t dst, const void* src, int srcBytes) {
    asm volatile("cp.async.cg.shared.global [%0], [%1], 16, %2;"
                 :: "r"(dst), "l"(src), "r"(srcBytes) : "memory");
}
#define CP_COMMIT() asm volatile("cp.async.commit_group;" ::: "memory")
template <int N>
__device__ __forceinline__ void cp_wait() {
    asm volatile("cp.async.wait_group %0;" :: "n"(N) : "memory");
}

__device__ __forceinline__ uint32_t pack_bf16(float lo, float hi) {
    uint32_t r;
    asm("cvt.rn.bf16x2.f32 %0, %1, %2;" : "=r"(r) : "f"(hi), "f"(lo));
    return r;
}
__device__ __forceinline__ float bf16_round(float v) {
    __nv_bfloat16 h = __float2bfloat16_rn(v);
    return __bfloat162float(h);
}

__device__ __forceinline__ void mma_bf16(float c[4], uint32_t a0, uint32_t a1,
                                         uint32_t a2, uint32_t a3,
                                         uint32_t b0, uint32_t b1) {
    asm("mma.sync.aligned.m16n8k16.row.col.f32.bf16.bf16.f32 "
        "{%0,%1,%2,%3},{%4,%5,%6,%7},{%8,%9},{%0,%1,%2,%3};"
        : "+f"(c[0]), "+f"(c[1]), "+f"(c[2]), "+f"(c[3])
        : "r"(a0), "r"(a1), "r"(a2), "r"(a3), "r"(b0), "r"(b1));
}

__device__ __forceinline__ void acc8(float* acc, uint4 u) {
    float2 f;
    f = __half22float2(*(__half2*)&u.x); acc[0] += f.x; acc[1] += f.y;
    f = __half22float2(*(__half2*)&u.y); acc[2] += f.x; acc[3] += f.y;
    f = __half22float2(*(__half2*)&u.z); acc[4] += f.x; acc[5] += f.y;
    f = __half22float2(*(__half2*)&u.w); acc[6] += f.x; acc[7] += f.y;
}

// ---------------- init: zero counters + dtype probe (block 0) ----------------
__global__ void k_init(const int* __restrict__ ei32) {
    int i = blockIdx.x * 256 + threadIdx.x;
    if (i < N_NODES) { g_deg[i] = 0; g_cur[i] = 0; }
    if (i == 0) g_total = 0;
    if (blockIdx.x == 0) {
        __shared__ int anyNZ;
        if (threadIdx.x == 0) anyNZ = 0;
        __syncthreads();
        int nz = 0;
        #pragma unroll
        for (int j = 0; j < 8; j++) {
            int idx = 2 * (threadIdx.x + 256 * j) + 1;
            if (ei32[idx] != 0) nz = 1;
        }
        if (nz) atomicOr(&anyNZ, 1);
        __syncthreads();
        if (threadIdx.x == 0) g_is64 = anyNZ ? 0 : 1;
    }
}

__device__ __forceinline__ int edge_at(const void* ei, long long idx) {
    if (g_is64) return (int)((const long long*)ei)[idx];
    return ((const int*)ei)[idx];
}

// ---------------- graph build ------------------------------------------------
__global__ void k_count(const void* __restrict__ ei) {
    int e = blockIdx.x * blockDim.x + threadIdx.x;
    if (e < N_EDGES) {
        int c = edge_at(ei, (long long)N_EDGES + e);
        if ((unsigned)c < N_NODES) atomicAdd(&g_deg[c], 1);
    }
}

__global__ void k_offa() {
    __shared__ int sh[256];
    __shared__ int base;
    int t = threadIdx.x;
    int i = blockIdx.x * 256 + t;
    int d = (i < N_NODES) ? g_deg[i] : 0;
    sh[t] = d;
    __syncthreads();
    #pragma unroll
    for (int off = 1; off < 256; off <<= 1) {
        int u = (t >= off) ? sh[t - off] : 0;
        __syncthreads();
        sh[t] += u;
        __syncthreads();
    }
    if (t == 255) base = atomicAdd(&g_total, sh[255]);
    __syncthreads();
    if (i < N_NODES) {
        g_off[i] = base + sh[t] - d;
        g_dinv[i] = rsqrtf((float)(d + 1));
    }
}

__global__ void k_fill(const void* __restrict__ ei) {
    int e = blockIdx.x * blockDim.x + threadIdx.x;
    if (e < N_EDGES) {
        int r = edge_at(ei, e);
        int c = edge_at(ei, (long long)N_EDGES + e);
        if ((unsigned)r >= N_NODES || (unsigned)c >= N_NODES) return;
        int pos = g_off[c] + atomicAdd(&g_cur[c], 1);
        if ((unsigned)pos < N_EDGES) g_src[pos] = r;
    }
}

// ---------------- layer-1 GEMM: fp32 X, cp.async + convert path --------------
// g_h16[m][n] = fp16( dinv[m] * sum_k X[m][k] W[k][n] )
__global__ void __launch_bounds__(256, 2) k_mgemm(const float* __restrict__ X,
                                                  const float* __restrict__ W) {
    __shared__ __align__(16) float sRaw[2][32 * 128];  // 32 KB
    __shared__ uint32_t sHi[16 * 128];                  // 8 KB
    __shared__ uint32_t sLo[16 * 128];                  // 8 KB

    __half2* H = g_h16;
    int tid = threadIdx.x, wid = tid >> 5, lane = tid & 31;
    int nbase = wid * 16;

    uint32_t Whi[8][2][2], Wlo[8][2][2];
    #pragma unroll
    for (int ks = 0; ks < 8; ks++) {
        #pragma unroll
        for (int nb = 0; nb < 2; nb++) {
            int col = nbase + nb * 8 + (lane >> 2);
            int k0  = ks * 16 + (lane & 3) * 2;
            float w00 = W[(k0 + 0) * 128 + col];
            float w01 = W[(k0 + 1) * 128 + col];
            float w10 = W[(k0 + 8) * 128 + col];
            float w11 = W[(k0 + 9) * 128 + col];
            float h00 = bf16_round(w00), h01 = bf16_round(w01);
            float h10 = bf16_round(w10), h11 = bf16_round(w11);
            Whi[ks][nb][0] = pack_bf16(h00, h01);
            Whi[ks][nb][1] = pack_bf16(h10, h11);
            Wlo[ks][nb][0] = pack_bf16(w00 - h00, w01 - h01);
            Wlo[ks][nb][1] = pack_bf16(w10 - h10, w11 - h11);
        }
    }

    int rowBase = blockIdx.x * 128;

    int sAddr[4];
    #pragma unroll
    for (int i = 0; i < 4; i++) {
        int lin = tid + 256 * i;
        int rl = lin >> 5, kq = lin & 31;
        int mb = rl >> 4, rloc = rl & 15;
        int ks = kq >> 2;
        int j = ((rloc >> 3) & 1) + (((kq >> 1) & 1) << 1);
        int slot = (rloc & 7) * 4 + 2 * (kq & 1);
        int slot_sw = slot ^ (ks << 2);
        sAddr[i] = (mb * 8 + ks) * 128 + slot_sw * 4 + j;
    }

    uint32_t rawAddr0 = smem_u32(&sRaw[0][0]);
    uint32_t rawAddr1 = smem_u32(&sRaw[1][0]);

    #pragma unroll
    for (int s = 0; s < 2; s++) {
        uint32_t base = s ? rawAddr1 : rawAddr0;
        #pragma unroll
        for (int i = 0; i < 4; i++) {
            int lin = tid + 256 * i;
            int rl = lin >> 5, kq = lin & 31;
            int gr = rowBase + s * 32 + rl;
            int ok = (gr < N_NODES);
            int grc = ok ? gr : 0;
            cp_async16(base + lin * 16, X + (size_t)grc * 128 + kq * 4, ok ? 16 : 0);
        }
        CP_COMMIT();
    }

    #pragma unroll 1
    for (int slab = 0; slab < 4; slab++) {
        int buf = slab & 1;
        cp_wait<1>();
        __syncthreads();

        #pragma unroll
        for (int i = 0; i < 4; i++) {
            int lin = tid + 256 * i;
            float4 v = *(const float4*)&sRaw[buf][lin * 4];
            int base = sAddr[i];
            float hx = bf16_round(v.x), hy = bf16_round(v.y);
            float hz = bf16_round(v.z), hw = bf16_round(v.w);
            sHi[base]     = pack_bf16(hx, hy);
            sHi[base + 4] = pack_bf16(hz, hw);
            sLo[base]     = pack_bf16(v.x - hx, v.y - hy);
            sLo[base + 4] = pack_bf16(v.z - hz, v.w - hw);
        }
        __syncthreads();

        if (slab < 2) {
            uint32_t base = buf ? rawAddr1 : rawAddr0;
            #pragma unroll
            for (int i = 0; i < 4; i++) {
                int lin = tid + 256 * i;
                int rl = lin >> 5, kq = lin & 31;
                int gr = rowBase + (slab + 2) * 32 + rl;
                int ok = (gr < N_NODES);
                int grc = ok ? gr : 0;
                cp_async16(base + lin * 16, X + (size_t)grc * 128 + kq * 4, ok ? 16 : 0);
            }
        }
        CP_COMMIT();

        #pragma unroll 1
        for (int mb = 0; mb < 2; mb++) {
            float a0[2][4], a1[2][4], a2[2][4];
            #pragma unroll
            for (int nb = 0; nb < 2; nb++)
                #pragma unroll
                for (int j = 0; j < 4; j++) { a0[nb][j] = 0.f; a1[nb][j] = 0.f; a2[nb][j] = 0.f; }

            #pragma unroll
            for (int ks = 0; ks < 8; ks++) {
                int idx = (mb * 8 + ks) * 128 + (lane ^ (ks << 2)) * 4;
                uint4 ah = *(const uint4*)&sHi[idx];
                uint4 al = *(const uint4*)&sLo[idx];
                #pragma unroll
                for (int nb = 0; nb < 2; nb++) {
                    mma_bf16(a0[nb], ah.x, ah.y, ah.z, ah.w, Whi[ks][nb][0], Whi[ks][nb][1]);
                    mma_bf16(a1[nb], al.x, al.y, al.z, al.w, Whi[ks][nb][0], Whi[ks][nb][1]);
                    mma_bf16(a2[nb], ah.x, ah.y, ah.z, ah.w, Wlo[ks][nb][0], Wlo[ks][nb][1]);
                }
            }

            int r0 = rowBase + slab * 32 + mb * 16 + (lane >> 2);
            int r1 = r0 + 8;
            float d0 = (r0 < N_NODES) ? g_dinv[r0] : 0.f;
            float d1 = (r1 < N_NODES) ? g_dinv[r1] : 0.f;
            #pragma unroll
            for (int nb = 0; nb < 2; nb++) {
                int cc = nbase + nb * 8 + (lane & 3) * 2;
                float s0 = a0[nb][0] + a1[nb][0] + a2[nb][0];
                float s1 = a0[nb][1] + a1[nb][1] + a2[nb][1];
                float s2 = a0[nb][2] + a1[nb][2] + a2[nb][2];
                float s3 = a0[nb][3] + a1[nb][3] + a2[nb][3];
                if (r0 < N_NODES)
                    H[(size_t)r0 * 64 + (cc >> 1)] = __floats2half2_rn(s0 * d0, s1 * d0);
                if (r1 < N_NODES)
                    H[(size_t)r1 * 64 + (cc >> 1)] = __floats2half2_rn(s2 * d1, s3 * d1);
            }
        }
    }
}

// ---------------- layer-2 GEMM: pre-fragmented bf16 hi/lo input --------------
// No convert pass: cp.async lands g_fhi/g_flo straight into frag smem.
__global__ void __launch_bounds__(256, 2) k_mgemmF(const float* __restrict__ W) {
    __shared__ uint32_t sHi[2][2048];   // 2 x 8 KB
    __shared__ uint32_t sLo[2][2048];   // 2 x 8 KB

    __half2* H = g_h16;
    int tid = threadIdx.x, wid = tid >> 5, lane = tid & 31;
    int nbase = wid * 16;

    uint32_t Whi[8][2][2], Wlo[8][2][2];
    #pragma unroll
    for (int ks = 0; ks < 8; ks++) {
        #pragma unroll
        for (int nb = 0; nb < 2; nb++) {
            int col = nbase + nb * 8 + (lane >> 2);
            int k0  = ks * 16 + (lane & 3) * 2;
            float w00 = W[(k0 + 0) * 128 + col];
            float w01 = W[(k0 + 1) * 128 + col];
            float w10 = W[(k0 + 8) * 128 + col];
            float w11 = W[(k0 + 9) * 128 + col];
            float h00 = bf16_round(w00), h01 = bf16_round(w01);
            float h10 = bf16_round(w10), h11 = bf16_round(w11);
            Whi[ks][nb][0] = pack_bf16(h00, h01);
            Whi[ks][nb][1] = pack_bf16(h10, h11);
            Wlo[ks][nb][0] = pack_bf16(w00 - h00, w01 - h01);
            Wlo[ks][nb][1] = pack_bf16(w10 - h10, w11 - h11);
        }
    }

    int rowBase = blockIdx.x * 128;
    size_t tbase = (size_t)blockIdx.x * 8192;   // per-tile: 4 slabs x 2048 u32

    uint32_t hiA[2] = { smem_u32(&sHi[0][0]), smem_u32(&sHi[1][0]) };
    uint32_t loA[2] = { smem_u32(&sLo[0][0]), smem_u32(&sLo[1][0]) };

    // prologue: slabs 0,1 (per slab: 512 hi chunks + 512 lo chunks, 16 B each)
    #pragma unroll
    for (int s = 0; s < 2; s++) {
        #pragma unroll
        for (int i = 0; i < 2; i++) {
            int ch = tid + 256 * i;
            cp_async16(hiA[s] + ch * 16, g_fhi + tbase + s * 2048 + ch * 4, 16);
            cp_async16(loA[s] + ch * 16, g_flo + tbase + s * 2048 + ch * 4, 16);
        }
        CP_COMMIT();
    }

    #pragma unroll 1
    for (int slab = 0; slab < 4; slab++) {
        int buf = slab & 1;
        cp_wait<1>();
        __syncthreads();   // slab's frags visible to all; prev compute done

        #pragma unroll 1
        for (int mb = 0; mb < 2; mb++) {
            float a0[2][4], a1[2][4], a2[2][4];
            #pragma unroll
            for (int nb = 0; nb < 2; nb++)
                #pragma unroll
                for (int j = 0; j < 4; j++) { a0[nb][j] = 0.f; a1[nb][j] = 0.f; a2[nb][j] = 0.f; }

            #pragma unroll
            for (int ks = 0; ks < 8; ks++) {
                int idx = (mb * 8 + ks) * 128 + (lane ^ (ks << 2)) * 4;
                uint4 ah = *(const uint4*)&sHi[buf][idx];
                uint4 al = *(const uint4*)&sLo[buf][idx];
                #pragma unroll
                for (int nb = 0; nb < 2; nb++) {
                    mma_bf16(a0[nb], ah.x, ah.y, ah.z, ah.w, Whi[ks][nb][0], Whi[ks][nb][1]);
                    mma_bf16(a1[nb], al.x, al.y, al.z, al.w, Whi[ks][nb][0], Whi[ks][nb][1]);
                    mma_bf16(a2[nb], ah.x, ah.y, ah.z, ah.w, Wlo[ks][nb][0], Wlo[ks][nb][1]);
                }
            }

            int r0 = rowBase + slab * 32 + mb * 16 + (lane >> 2);
            int r1 = r0 + 8;
            float d0 = (r0 < N_NODES) ? g_dinv[r0] : 0.f;
            float d1 = (r1 < N_NODES) ? g_dinv[r1] : 0.f;
            #pragma unroll
            for (int nb = 0; nb < 2; nb++) {
                int cc = nbase + nb * 8 + (lane & 3) * 2;
                float s0 = a0[nb][0] + a1[nb][0] + a2[nb][0];
                float s1 = a0[nb][1] + a1[nb][1] + a2[nb][1];
                float s2 = a0[nb][2] + a1[nb][2] + a2[nb][2];
                float s3 = a0[nb][3] + a1[nb][3] + a2[nb][3];
                if (r0 < N_NODES)
                    H[(size_t)r0 * 64 + (cc >> 1)] = __floats2half2_rn(s0 * d0, s1 * d0);
                if (r1 < N_NODES)
                    H[(size_t)r1 * 64 + (cc >> 1)] = __floats2half2_rn(s2 * d1, s3 * d1);
            }
        }
        __syncthreads();   // all reads of buf done before refilling it

        if (slab < 2) {
            #pragma unroll
            for (int i = 0; i < 2; i++) {
                int ch = tid + 256 * i;
                cp_async16(hiA[buf] + ch * 16, g_fhi + tbase + (slab + 2) * 2048 + ch * 4, 16);
                cp_async16(loA[buf] + ch * 16, g_flo + tbase + (slab + 2) * 2048 + ch * 4, 16);
            }
        }
        CP_COMMIT();
    }
}

// ---------------- layer-1 agg: gather + write bf16 hi/lo fragments -----------
// h[c] = dinv[c]*(xts16[c] + sum_in xts16[s]) + bias, emitted in frag order.
// 512 threads = 16 aligned nodes = exactly one (tile,slab,mb) frag region.
__global__ void __launch_bounds__(512) k_aggF(const float* __restrict__ bias) {
    __shared__ uint32_t stH[16 * 64];
    __shared__ uint32_t stL[16 * 64];

    int tid = threadIdx.x, wid = tid >> 5, lane = tid & 31;
    int c = blockIdx.x * 16 + wid;               // 6250*16 = 100000 exact
    int sub = lane >> 4;
    int ln  = lane & 15;

    const uint4* hv4 = (const uint4*)g_h16;

    float acc[8];
    #pragma unroll
    for (int j = 0; j < 8; j++) acc[j] = 0.f;

    if (sub == 0) acc8(acc, hv4[(size_t)c * 16 + ln]);   // self term

    int e0 = g_off[c];
    int e1 = e0 + g_deg[c];
    int e = e0;
    for (; e + 8 <= e1; e += 8) {
        int s0 = __ldg(&g_src[e     + sub]);
        int s1 = __ldg(&g_src[e + 2 + sub]);
        int s2 = __ldg(&g_src[e + 4 + sub]);
        int s3 = __ldg(&g_src[e + 6 + sub]);
        uint4 u0 = hv4[(size_t)s0 * 16 + ln];
        uint4 u1 = hv4[(size_t)s1 * 16 + ln];
        uint4 u2 = hv4[(size_t)s2 * 16 + ln];
        uint4 u3 = hv4[(size_t)s3 * 16 + ln];
        acc8(acc, u0); acc8(acc, u1); acc8(acc, u2); acc8(acc, u3);
    }
    for (; e < e1; e += 2) {
        int idx = e + sub;
        if (idx < e1) {
            int s = __ldg(&g_src[idx]);
            acc8(acc, hv4[(size_t)s * 16 + ln]);
        }
    }

    float res[8];
    #pragma unroll
    for (int j = 0; j < 8; j++)
        res[j] = acc[j] + __shfl_xor_sync(0xFFFFFFFFu, acc[j], 16);

    float dc = g_dinv[c];
    int o0 = sub * 4;
    int q = ln * 2 + sub;                       // float4 slot 0..31
    float4 b = ((const float4*)bias)[q];
    float v0 = res[o0 + 0] * dc + b.x;
    float v1 = res[o0 + 1] * dc + b.y;
    float v2 = res[o0 + 2] * dc + b.z;
    float v3 = res[o0 + 3] * dc + b.w;

    float h0 = bf16_round(v0), h1 = bf16_round(v1);
    float h2 = bf16_round(v2), h3 = bf16_round(v3);
    stH[wid * 64 + 2 * q    ] = pack_bf16(h0, h1);
    stH[wid * 64 + 2 * q + 1] = pack_bf16(h2, h3);
    stL[wid * 64 + 2 * q    ] = pack_bf16(v0 - h0, v1 - h1);
    stL[wid * 64 + 2 * q + 1] = pack_bf16(v2 - h2, v3 - h3);
    __syncthreads();

    // cooperative frag-ordered write: 2 arrays x 256 uint4 chunks
    int c0 = blockIdx.x * 16;
    int tile = c0 >> 7, slab = (c0 >> 5) & 3, mb = (c0 >> 4) & 1;
    size_t rbase = ((size_t)tile * 8 + slab * 2 + mb) * 1024;

    int arr = tid >> 8;        // 0 = hi, 1 = lo
    int ch  = tid & 255;
    uint32_t w[4];
    #pragma unroll
    for (int u4 = 0; u4 < 4; u4++) {
        int u = ch * 4 + u4;
        int ks = u >> 7, rem = u & 127;
        int j = rem & 3;
        int pairsel = (rem >> 2) & 1;
        int slot_sw = (rem >> 3) << 1;
        int slot = slot_sw ^ (ks << 2);
        int rl = ((j & 1) << 3) | (slot >> 2);
        int kq = (ks << 2) | ((j >> 1) << 1) | ((slot >> 1) & 1);
        int p  = kq * 2 + pairsel;
        w[u4] = arr ? stL[rl * 64 + p] : stH[rl * 64 + p];
    }
    uint32_t* dst = arr ? g_flo : g_fhi;
    *(uint4*)&dst[rbase + ch * 4] = *(uint4*)w;
}

// ---------------- layer-2 agg: gather + fp32 output --------------------------
__global__ void __launch_bounds__(256) k_agg(const float* __restrict__ bias,
                                             float* __restrict__ out) {
    int gw = (blockIdx.x * blockDim.x + threadIdx.x) >> 5;
    int lane = threadIdx.x & 31;
    if (gw >= N_NODES) return;
    int c = gw;
    int sub = lane >> 4;
    int ln  = lane & 15;

    const uint4* hv4 = (const uint4*)g_h16;

    float acc[8];
    #pragma unroll
    for (int j = 0; j < 8; j++) acc[j] = 0.f;

    if (sub == 0) acc8(acc, hv4[(size_t)c * 16 + ln]);

    int e0 = g_off[c];
    int e1 = e0 + g_deg[c];
    int e = e0;
    for (; e + 8 <= e1; e += 8) {
        int s0 = __ldg(&g_src[e     + sub]);
        int s1 = __ldg(&g_src[e + 2 + sub]);
        int s2 = __ldg(&g_src[e + 4 + sub]);
        int s3 = __ldg(&g_src[e + 6 + sub]);
        uint4 u0 = hv4[(size_t)s0 * 16 + ln];
        uint4 u1 = hv4[(size_t)s1 * 16 + ln];
        uint4 u2 = hv4[(size_t)s2 * 16 + ln];
        uint4 u3 = hv4[(size_t)s3 * 16 + ln];
        acc8(acc, u0); acc8(acc, u1); acc8(acc, u2); acc8(acc, u3);
    }
    for (; e < e1; e += 2) {
        int idx = e + sub;
        if (idx < e1) {
            int s = __ldg(&g_src[idx]);
            acc8(acc, hv4[(size_t)s * 16 + ln]);
        }
    }

    float res[8];
    #pragma unroll
    for (int j = 0; j < 8; j++)
        res[j] = acc[j] + __shfl_xor_sync(0xFFFFFFFFu, acc[j], 16);

    float dc = g_dinv[c];
    int o0 = sub * 4;
    int fslot = ln * 2 + sub;
    float4 b = ((const float4*)bias)[fslot];
    float4 o = make_float4(res[o0 + 0] * dc + b.x, res[o0 + 1] * dc + b.y,
                           res[o0 + 2] * dc + b.z, res[o0 + 3] * dc + b.w);
    ((float4*)out)[(size_t)c * 32 + fslot] = o;
}

// ---------------- launch -----------------------------------------------------
extern "C" void kernel_launch(void* const* d_in, const int* in_sizes, int n_in,
                              void* d_out, int out_size) {
    const float* X  = (const float*)d_in[0];
    const void*  EI = d_in[1];
    const float* W1 = (const float*)d_in[2];
    const float* B1 = (const float*)d_in[3];
    const float* W2 = (const float*)d_in[4];
    const float* B2 = (const float*)d_in[5];
    float*       out = (float*)d_out;

    const int edgeBlocks = (N_EDGES + 255) / 256;
    const int aggBlocks  = (N_NODES * 32 + 255) / 256;
    const int aggFBlocks = N_NODES / 16;              // 6250, exact

    k_init<<<NBLK, 256>>>((const int*)EI);            // 0
    k_count<<<edgeBlocks, 256>>>(EI);                 // 1
    k_offa<<<NBLK, 256>>>();                          // 2
    k_mgemm<<<N_TILES, 256>>>(X, W1);                 // 3 <- profiled launch
    k_fill<<<edgeBlocks, 256>>>(EI);                  // 4
    k_aggF<<<aggFBlocks, 512>>>(B1);                  // 5: h -> g_fhi/g_flo
    k_mgemmF<<<N_TILES, 256>>>(W2);                   // 6: xts16 -> g_h16
    k_agg<<<aggBlocks, 256>>>(B2, out);               // 7: -> d_out
}

// round 14
// speedup vs baseline: 1.0937x; 1.0937x over previous
#include <cuda_runtime.h>
#include <cuda_bf16.h>
#include <cuda_fp16.h>
#include <cstdint>

#define N_NODES 100000
#define N_EDGES 1600000
#define HID 128
#define NBLK ((N_NODES + 255) / 256)     // 391
#define N_TILES ((N_NODES + 127) / 128)  // 782
#define GEMM_GRID 296                    // 2 CTAs x 148 SMs, persistent

// ---------------- scratch ----------------------------------------------------
__device__ __align__(16) __half2 g_h16[(size_t)N_NODES * 64]; // xts in fp16
__device__ __align__(16) float g_buf1[(size_t)N_NODES * HID]; // layer-1 hidden (fp32)
__device__ float g_dinv[N_NODES];
__device__ int   g_deg[N_NODES];
__device__ int   g_cur[N_NODES];
__device__ int   g_off[N_NODES];
__device__ int   g_src[N_EDGES];
__device__ int   g_total;
__device__ int   g_is64;

// ---------------- helpers ----------------------------------------------------
__device__ __forceinline__ uint32_t smem_u32(const void* p) {
    uint32_t a;
    asm("{ .reg .u64 t; cvta.to.shared.u64 t, %1; cvt.u32.u64 %0, t; }"
        : "=r"(a) : "l"(p));
    return a;
}
__device__ __forceinline__ void cp_async16(uint32_t dst, const void* src, int srcBytes) {
    asm volatile("cp.async.cg.shared.global [%0], [%1], 16, %2;"
                 :: "r"(dst), "l"(src), "r"(srcBytes) : "memory");
}
#define CP_COMMIT() asm volatile("cp.async.commit_group;" ::: "memory")
template <int N>
__device__ __forceinline__ void cp_wait() {
    asm volatile("cp.async.wait_group %0;" :: "n"(N) : "memory");
}

__device__ __forceinline__ uint32_t pack_bf16(float lo, float hi) {
    uint32_t r;
    asm("cvt.rn.bf16x2.f32 %0, %1, %2;" : "=r"(r) : "f"(hi), "f"(lo));
    return r;
}
__device__ __forceinline__ float bf16_round(float v) {
    __nv_bfloat16 h = __float2bfloat16_rn(v);
    return __bfloat162float(h);
}

__device__ __forceinline__ void mma_bf16(float c[4], uint32_t a0, uint32_t a1,
                                         uint32_t a2, uint32_t a3,
                                         uint32_t b0, uint32_t b1) {
    asm("mma.sync.aligned.m16n8k16.row.col.f32.bf16.bf16.f32 "
        "{%0,%1,%2,%3},{%4,%5,%6,%7},{%8,%9},{%0,%1,%2,%3};"
        : "+f"(c[0]), "+f"(c[1]), "+f"(c[2]), "+f"(c[3])
        : "r"(a0), "r"(a1), "r"(a2), "r"(a3), "r"(b0), "r"(b1));
}

__device__ __forceinline__ void acc8(float* acc, uint4 u) {
    float2 f;
    f = __half22float2(*(__half2*)&u.x); acc[0] += f.x; acc[1] += f.y;
    f = __half22float2(*(__half2*)&u.y); acc[2] += f.x; acc[3] += f.y;
    f = __half22float2(*(__half2*)&u.z); acc[4] += f.x; acc[5] += f.y;
    f = __half22float2(*(__half2*)&u.w); acc[6] += f.x; acc[7] += f.y;
}

// ---------------- init: zero counters + dtype probe (block 0) ----------------
__global__ void k_init(const int* __restrict__ ei32) {
    int i = blockIdx.x * 256 + threadIdx.x;
    if (i < N_NODES) { g_deg[i] = 0; g_cur[i] = 0; }
    if (i == 0) g_total = 0;
    if (blockIdx.x == 0) {
        __shared__ int anyNZ;
        if (threadIdx.x == 0) anyNZ = 0;
        __syncthreads();
        int nz = 0;
        #pragma unroll
        for (int j = 0; j < 8; j++) {
            int idx = 2 * (threadIdx.x + 256 * j) + 1;
            if (ei32[idx] != 0) nz = 1;
        }
        if (nz) atomicOr(&anyNZ, 1);
        __syncthreads();
        if (threadIdx.x == 0) g_is64 = anyNZ ? 0 : 1;
    }
}

__device__ __forceinline__ int edge_at(const void* ei, long long idx) {
    if (g_is64) return (int)((const long long*)ei)[idx];
    return ((const int*)ei)[idx];
}

// ---------------- graph build ------------------------------------------------
__global__ void k_count(const void* __restrict__ ei) {
    int e = blockIdx.x * blockDim.x + threadIdx.x;
    if (e < N_EDGES) {
        int c = edge_at(ei, (long long)N_EDGES + e);
        if ((unsigned)c < N_NODES) atomicAdd(&g_deg[c], 1);
    }
}

__global__ void k_offa() {
    __shared__ int sh[256];
    __shared__ int base;
    int t = threadIdx.x;
    int i = blockIdx.x * 256 + t;
    int d = (i < N_NODES) ? g_deg[i] : 0;
    sh[t] = d;
    __syncthreads();
    #pragma unroll
    for (int off = 1; off < 256; off <<= 1) {
        int u = (t >= off) ? sh[t - off] : 0;
        __syncthreads();
        sh[t] += u;
        __syncthreads();
    }
    if (t == 255) base = atomicAdd(&g_total, sh[255]);
    __syncthreads();
    if (i < N_NODES) {
        g_off[i] = base + sh[t] - d;
        g_dinv[i] = rsqrtf((float)(d + 1));
    }
}

__global__ void k_fill(const void* __restrict__ ei) {
    int e = blockIdx.x * blockDim.x + threadIdx.x;
    if (e < N_EDGES) {
        int r = edge_at(ei, e);
        int c = edge_at(ei, (long long)N_EDGES + e);
        if ((unsigned)r >= N_NODES || (unsigned)c >= N_NODES) return;
        int pos = g_off[c] + atomicAdd(&g_cur[c], 1);
        if ((unsigned)pos < N_EDGES) g_src[pos] = r;
    }
}

// ---------------- bf16 3-term mma.sync GEMM, persistent + cp.async -----------
// g_h16[m][n] = fp16( dinv[m] * sum_k X[m][k] W[k][n] )
__global__ void __launch_bounds__(256, 2) k_mgemm(const float* __restrict__ Xext,
                                                  const float* __restrict__ W,
                                                  int srcSel) {
    __shared__ __align__(16) float sRaw[2][32 * 128];  // 32 KB
    __shared__ uint32_t sHi[16 * 128];                  // 8 KB
    __shared__ uint32_t sLo[16 * 128];                  // 8 KB

    const float* X = srcSel ? g_buf1 : Xext;
    __half2*     H = g_h16;

    int tid = threadIdx.x, wid = tid >> 5, lane = tid & 31;
    int nbase = wid * 16;

    // ---- W fragments (hi+lo) in registers, once per persistent CTA ----
    uint32_t Whi[8][2][2], Wlo[8][2][2];
    #pragma unroll
    for (int ks = 0; ks < 8; ks++) {
        #pragma unroll
        for (int nb = 0; nb < 2; nb++) {
            int col = nbase + nb * 8 + (lane >> 2);
            int k0  = ks * 16 + (lane & 3) * 2;
            float w00 = W[(k0 + 0) * 128 + col];
            float w01 = W[(k0 + 1) * 128 + col];
            float w10 = W[(k0 + 8) * 128 + col];
            float w11 = W[(k0 + 9) * 128 + col];
            float h00 = bf16_round(w00), h01 = bf16_round(w01);
            float h10 = bf16_round(w10), h11 = bf16_round(w11);
            Whi[ks][nb][0] = pack_bf16(h00, h01);
            Whi[ks][nb][1] = pack_bf16(h10, h11);
            Wlo[ks][nb][0] = pack_bf16(w00 - h00, w01 - h01);
            Wlo[ks][nb][1] = pack_bf16(w10 - h10, w11 - h11);
        }
    }

    // frag store addresses (loop-invariant)
    int sAddr[4];
    #pragma unroll
    for (int i = 0; i < 4; i++) {
        int lin = tid + 256 * i;
        int rl = lin >> 5, kq = lin & 31;
        int mb = rl >> 4, rloc = rl & 15;
        int ks = kq >> 2;
        int j = ((rloc >> 3) & 1) + (((kq >> 1) & 1) << 1);
        int slot = (rloc & 7) * 4 + 2 * (kq & 1);
        int slot_sw = slot ^ (ks << 2);
        sAddr[i] = (mb * 8 + ks) * 128 + slot_sw * 4 + j;
    }

    uint32_t rawAddr0 = smem_u32(&sRaw[0][0]);
    uint32_t rawAddr1 = smem_u32(&sRaw[1][0]);

    // ---- persistent tile loop ----
    #pragma unroll 1
    for (int tile = blockIdx.x; tile < N_TILES; tile += GEMM_GRID) {
        int rowBase = tile * 128;

        // prologue: issue slabs 0, 1
        #pragma unroll
        for (int s = 0; s < 2; s++) {
            uint32_t base = s ? rawAddr1 : rawAddr0;
            #pragma unroll
            for (int i = 0; i < 4; i++) {
                int lin = tid + 256 * i;
                int rl = lin >> 5, kq = lin & 31;
                int gr = rowBase + s * 32 + rl;
                int ok = (gr < N_NODES);
                int grc = ok ? gr : 0;
                cp_async16(base + lin * 16, X + (size_t)grc * 128 + kq * 4, ok ? 16 : 0);
            }
            CP_COMMIT();
        }

        #pragma unroll 1
        for (int slab = 0; slab < 4; slab++) {
            int buf = slab & 1;
            cp_wait<1>();
            __syncthreads();

            // convert raw fp32 -> bf16 hi/lo fragments
            #pragma unroll
            for (int i = 0; i < 4; i++) {
                int lin = tid + 256 * i;
                float4 v = *(const float4*)&sRaw[buf][lin * 4];
                int base = sAddr[i];
                float hx = bf16_round(v.x), hy = bf16_round(v.y);
                float hz = bf16_round(v.z), hw = bf16_round(v.w);
                sHi[base]     = pack_bf16(hx, hy);
                sHi[base + 4] = pack_bf16(hz, hw);
                sLo[base]     = pack_bf16(v.x - hx, v.y - hy);
                sLo[base + 4] = pack_bf16(v.z - hz, v.w - hw);
            }
            __syncthreads();

            // refill drained buffer with slab+2
            if (slab < 2) {
                uint32_t base = buf ? rawAddr1 : rawAddr0;
                #pragma unroll
                for (int i = 0; i < 4; i++) {
                    int lin = tid + 256 * i;
                    int rl = lin >> 5, kq = lin & 31;
                    int gr = rowBase + (slab + 2) * 32 + rl;
                    int ok = (gr < N_NODES);
                    int grc = ok ? gr : 0;
                    cp_async16(base + lin * 16, X + (size_t)grc * 128 + kq * 4, ok ? 16 : 0);
                }
            }
            CP_COMMIT();

            // compute 2 m-blocks
            #pragma unroll 1
            for (int mb = 0; mb < 2; mb++) {
                float a0[2][4], a1[2][4], a2[2][4];
                #pragma unroll
                for (int nb = 0; nb < 2; nb++)
                    #pragma unroll
                    for (int j = 0; j < 4; j++) { a0[nb][j] = 0.f; a1[nb][j] = 0.f; a2[nb][j] = 0.f; }

                #pragma unroll
                for (int ks = 0; ks < 8; ks++) {
                    int idx = (mb * 8 + ks) * 128 + (lane ^ (ks << 2)) * 4;
                    uint4 ah = *(const uint4*)&sHi[idx];
                    uint4 al = *(const uint4*)&sLo[idx];
                    #pragma unroll
                    for (int nb = 0; nb < 2; nb++) {
                        mma_bf16(a0[nb], ah.x, ah.y, ah.z, ah.w, Whi[ks][nb][0], Whi[ks][nb][1]);
                        mma_bf16(a1[nb], al.x, al.y, al.z, al.w, Whi[ks][nb][0], Whi[ks][nb][1]);
                        mma_bf16(a2[nb], ah.x, ah.y, ah.z, ah.w, Wlo[ks][nb][0], Wlo[ks][nb][1]);
                    }
                }

                int r0 = rowBase + slab * 32 + mb * 16 + (lane >> 2);
                int r1 = r0 + 8;
                float d0 = (r0 < N_NODES) ? g_dinv[r0] : 0.f;
                float d1 = (r1 < N_NODES) ? g_dinv[r1] : 0.f;
                #pragma unroll
                for (int nb = 0; nb < 2; nb++) {
                    int cc = nbase + nb * 8 + (lane & 3) * 2;
                    float s0 = a0[nb][0] + a1[nb][0] + a2[nb][0];
                    float s1 = a0[nb][1] + a1[nb][1] + a2[nb][1];
                    float s2 = a0[nb][2] + a1[nb][2] + a2[nb][2];
                    float s3 = a0[nb][3] + a1[nb][3] + a2[nb][3];
                    if (r0 < N_NODES)
                        H[(size_t)r0 * 64 + (cc >> 1)] = __floats2half2_rn(s0 * d0, s1 * d0);
                    if (r1 < N_NODES)
                        H[(size_t)r1 * 64 + (cc >> 1)] = __floats2half2_rn(s2 * d1, s3 * d1);
                }
            }
        }
        __syncthreads();   // frag buffers fully consumed before next tile reuses them
    }
}

// ---------------- aggregation: 2 edges per LDG.128, shfl combine -------------
// out[c] = dinv[c]*(xts16[c] + sum_in xts16[s]) + bias
__global__ void __launch_bounds__(256) k_agg(const float* __restrict__ bias,
                                             float* __restrict__ outExt,
                                             int useExtOut) {
    int gw = (blockIdx.x * blockDim.x + threadIdx.x) >> 5;
    int lane = threadIdx.x & 31;
    if (gw >= N_NODES) return;
    int c = gw;
    int sub = lane >> 4;
    int ln  = lane & 15;

    const uint4* hv4 = (const uint4*)g_h16;
    float*       out = useExtOut ? outExt : g_buf1;

    float acc[8];
    #pragma unroll
    for (int j = 0; j < 8; j++) acc[j] = 0.f;

    if (sub == 0) acc8(acc, hv4[(size_t)c * 16 + ln]);   // self term

    int e0 = g_off[c];
    int e1 = e0 + g_deg[c];
    int e = e0;

    for (; e + 8 <= e1; e += 8) {
        int s0 = __ldg(&g_src[e     + sub]);
        int s1 = __ldg(&g_src[e + 2 + sub]);
        int s2 = __ldg(&g_src[e + 4 + sub]);
        int s3 = __ldg(&g_src[e + 6 + sub]);
        uint4 u0 = hv4[(size_t)s0 * 16 + ln];
        uint4 u1 = hv4[(size_t)s1 * 16 + ln];
        uint4 u2 = hv4[(size_t)s2 * 16 + ln];
        uint4 u3 = hv4[(size_t)s3 * 16 + ln];
        acc8(acc, u0); acc8(acc, u1); acc8(acc, u2); acc8(acc, u3);
    }
    for (; e < e1; e += 2) {
        int idx = e + sub;
        if (idx < e1) {
            int s = __ldg(&g_src[idx]);
            acc8(acc, hv4[(size_t)s * 16 + ln]);
        }
    }

    float res[8];
    #pragma unroll
    for (int j = 0; j < 8; j++)
        res[j] = acc[j] + __shfl_xor_sync(0xFFFFFFFFu, acc[j], 16);

    float dc = g_dinv[c];
    int o0 = sub * 4;
    int fslot = ln * 2 + sub;
    float4 b = ((const float4*)bias)[fslot];
    float4 o = make_float4(res[o0 + 0] * dc + b.x, res[o0 + 1] * dc + b.y,
                           res[o0 + 2] * dc + b.z, res[o0 + 3] * dc + b.w);
    ((float4*)out)[(size_t)c * 32 + fslot] = o;
}

// ---------------- launch -----------------------------------------------------
extern "C" void kernel_launch(void* const* d_in, const int* in_sizes, int n_in,
                              void* d_out, int out_size) {
    const float* X  = (const float*)d_in[0];
    const void*  EI = d_in[1];
    const float* W1 = (const float*)d_in[2];
    const float* B1 = (const float*)d_in[3];
    const float* W2 = (const float*)d_in[4];
    const float* B2 = (const float*)d_in[5];
    float*       out = (float*)d_out;

    const int edgeBlocks = (N_EDGES + 255) / 256;
    const int aggBlocks  = (N_NODES * 32 + 255) / 256;

    k_init<<<NBLK, 256>>>((const int*)EI);            // 0
    k_count<<<edgeBlocks, 256>>>(EI);                 // 1
    k_offa<<<NBLK, 256>>>();                          // 2
    k_mgemm<<<GEMM_GRID, 256>>>(X, W1, /*src=*/0);    // 3 <- profiled launch
    k_fill<<<edgeBlocks, 256>>>(EI);                  // 4
    k_agg<<<aggBlocks, 256>>>(B1, out, 0);            // 5: h -> buf1
    k_mgemm<<<GEMM_GRID, 256>>>(nullptr, W2, /*src=*/1); // 6
    k_agg<<<aggBlocks, 256>>>(B2, out, 1);            // 7: -> d_out
}

// round 15
// speedup vs baseline: 1.0980x; 1.0040x over previous
#include <cuda_runtime.h>
#include <cuda_bf16.h>
#include <cuda_fp16.h>
#include <cstdint>

#define N_NODES 100000
#define N_EDGES 1600000
#define HID 128
#define NBLK ((N_NODES + 255) / 256)     // 391
#define N_TILES ((N_NODES + 127) / 128)  // 782
#define GEMM_GRID 296                    // 2 CTAs x 148 SMs, persistent

// ---------------- scratch ----------------------------------------------------
__device__ __align__(16) __half2 g_h16[(size_t)N_NODES * 64]; // xts in fp16
__device__ __align__(16) float g_buf1[(size_t)N_NODES * HID]; // layer-1 hidden (fp32)
__device__ float g_dinv[N_NODES];
__device__ int   g_deg[N_NODES];
__device__ int   g_cur[N_NODES];
__device__ int   g_off[N_NODES];
__device__ int   g_src[N_EDGES];
__device__ int   g_total;
__device__ int   g_is64;

// ---------------- helpers ----------------------------------------------------
__device__ __forceinline__ uint32_t smem_u32(const void* p) {
    uint32_t a;
    asm("{ .reg .u64 t; cvta.to.shared.u64 t, %1; cvt.u32.u64 %0, t; }"
        : "=r"(a) : "l"(p));
    return a;
}
__device__ __forceinline__ void cp_async16(uint32_t dst, const void* src, int srcBytes) {
    asm volatile("cp.async.cg.shared.global [%0], [%1], 16, %2;"
                 :: "r"(dst), "l"(src), "r"(srcBytes) : "memory");
}
#define CP_COMMIT() asm volatile("cp.async.commit_group;" ::: "memory")
template <int N>
__device__ __forceinline__ void cp_wait() {
    asm volatile("cp.async.wait_group %0;" :: "n"(N) : "memory");
}

__device__ __forceinline__ uint32_t pack_bf16(float lo, float hi) {
    uint32_t r;
    asm("cvt.rn.bf16x2.f32 %0, %1, %2;" : "=r"(r) : "f"(hi), "f"(lo));
    return r;
}
__device__ __forceinline__ float bf16_round(float v) {
    __nv_bfloat16 h = __float2bfloat16_rn(v);
    return __bfloat162float(h);
}

__device__ __forceinline__ void mma_bf16(float c[4], uint32_t a0, uint32_t a1,
                                         uint32_t a2, uint32_t a3,
                                         uint32_t b0, uint32_t b1) {
    asm("mma.sync.aligned.m16n8k16.row.col.f32.bf16.bf16.f32 "
        "{%0,%1,%2,%3},{%4,%5,%6,%7},{%8,%9},{%0,%1,%2,%3};"
        : "+f"(c[0]), "+f"(c[1]), "+f"(c[2]), "+f"(c[3])
        : "r"(a0), "r"(a1), "r"(a2), "r"(a3), "r"(b0), "r"(b1));
}

__device__ __forceinline__ void acc8(float* acc, uint4 u) {
    float2 f;
    f = __half22float2(*(__half2*)&u.x); acc[0] += f.x; acc[1] += f.y;
    f = __half22float2(*(__half2*)&u.y); acc[2] += f.x; acc[3] += f.y;
    f = __half22float2(*(__half2*)&u.z); acc[4] += f.x; acc[5] += f.y;
    f = __half22float2(*(__half2*)&u.w); acc[6] += f.x; acc[7] += f.y;
}

// ---------------- init: zero counters + dtype probe (block 0) ----------------
__global__ void k_init(const int* __restrict__ ei32) {
    int i = blockIdx.x * 256 + threadIdx.x;
    if (i < N_NODES) { g_deg[i] = 0; g_cur[i] = 0; }
    if (i == 0) g_total = 0;
    if (blockIdx.x == 0) {
        __shared__ int anyNZ;
        if (threadIdx.x == 0) anyNZ = 0;
        __syncthreads();
        int nz = 0;
        #pragma unroll
        for (int j = 0; j < 8; j++) {
            int idx = 2 * (threadIdx.x + 256 * j) + 1;
            if (ei32[idx] != 0) nz = 1;
        }
        if (nz) atomicOr(&anyNZ, 1);
        __syncthreads();
        if (threadIdx.x == 0) g_is64 = anyNZ ? 0 : 1;
    }
}

__device__ __forceinline__ int edge_at(const void* ei, long long idx) {
    if (g_is64) return (int)((const long long*)ei)[idx];
    return ((const int*)ei)[idx];
}

// ---------------- graph build ------------------------------------------------
__global__ void k_count(const void* __restrict__ ei) {
    int e = blockIdx.x * blockDim.x + threadIdx.x;
    if (e < N_EDGES) {
        int c = edge_at(ei, (long long)N_EDGES + e);
        if ((unsigned)c < N_NODES) atomicAdd(&g_deg[c], 1);
    }
}

__global__ void k_offa() {
    __shared__ int sh[256];
    __shared__ int base;
    int t = threadIdx.x;
    int i = blockIdx.x * 256 + t;
    int d = (i < N_NODES) ? g_deg[i] : 0;
    sh[t] = d;
    __syncthreads();
    #pragma unroll
    for (int off = 1; off < 256; off <<= 1) {
        int u = (t >= off) ? sh[t - off] : 0;
        __syncthreads();
        sh[t] += u;
        __syncthreads();
    }
    if (t == 255) base = atomicAdd(&g_total, sh[255]);
    __syncthreads();
    if (i < N_NODES) {
        g_off[i] = base + sh[t] - d;
        g_dinv[i] = rsqrtf((float)(d + 1));
    }
}

__global__ void k_fill(const void* __restrict__ ei) {
    int e = blockIdx.x * blockDim.x + threadIdx.x;
    if (e < N_EDGES) {
        int r = edge_at(ei, e);
        int c = edge_at(ei, (long long)N_EDGES + e);
        if ((unsigned)r >= N_NODES || (unsigned)c >= N_NODES) return;
        int pos = g_off[c] + atomicAdd(&g_cur[c], 1);
        if ((unsigned)pos < N_EDGES) g_src[pos] = r;
    }
}

// ---------------- bf16 3-term mma.sync GEMM, persistent + cp.async -----------
// g_h16[m][n] = fp16( dinv[m] * sum_k X[m][k] W[k][n] )
__global__ void __launch_bounds__(256, 2) k_mgemm(const float* __restrict__ Xext,
                                                  const float* __restrict__ W,
                                                  int srcSel) {
    __shared__ __align__(16) float sRaw[2][32 * 128];  // 32 KB
    __shared__ uint32_t sHi[16 * 128];                  // 8 KB
    __shared__ uint32_t sLo[16 * 128];                  // 8 KB

    const float* X = srcSel ? g_buf1 : Xext;
    __half2*     H = g_h16;

    int tid = threadIdx.x, wid = tid >> 5, lane = tid & 31;
    int nbase = wid * 16;

    uint32_t Whi[8][2][2], Wlo[8][2][2];
    #pragma unroll
    for (int ks = 0; ks < 8; ks++) {
        #pragma unroll
        for (int nb = 0; nb < 2; nb++) {
            int col = nbase + nb * 8 + (lane >> 2);
            int k0  = ks * 16 + (lane & 3) * 2;
            float w00 = W[(k0 + 0) * 128 + col];
            float w01 = W[(k0 + 1) * 128 + col];
            float w10 = W[(k0 + 8) * 128 + col];
            float w11 = W[(k0 + 9) * 128 + col];
            float h00 = bf16_round(w00), h01 = bf16_round(w01);
            float h10 = bf16_round(w10), h11 = bf16_round(w11);
            Whi[ks][nb][0] = pack_bf16(h00, h01);
            Whi[ks][nb][1] = pack_bf16(h10, h11);
            Wlo[ks][nb][0] = pack_bf16(w00 - h00, w01 - h01);
            Wlo[ks][nb][1] = pack_bf16(w10 - h10, w11 - h11);
        }
    }

    int sAddr[4];
    #pragma unroll
    for (int i = 0; i < 4; i++) {
        int lin = tid + 256 * i;
        int rl = lin >> 5, kq = lin & 31;
        int mb = rl >> 4, rloc = rl & 15;
        int ks = kq >> 2;
        int j = ((rloc >> 3) & 1) + (((kq >> 1) & 1) << 1);
        int slot = (rloc & 7) * 4 + 2 * (kq & 1);
        int slot_sw = slot ^ (ks << 2);
        sAddr[i] = (mb * 8 + ks) * 128 + slot_sw * 4 + j;
    }

    uint32_t rawAddr0 = smem_u32(&sRaw[0][0]);
    uint32_t rawAddr1 = smem_u32(&sRaw[1][0]);

    #pragma unroll 1
    for (int tile = blockIdx.x; tile < N_TILES; tile += GEMM_GRID) {
        int rowBase = tile * 128;

        #pragma unroll
        for (int s = 0; s < 2; s++) {
            uint32_t base = s ? rawAddr1 : rawAddr0;
            #pragma unroll
            for (int i = 0; i < 4; i++) {
                int lin = tid + 256 * i;
                int rl = lin >> 5, kq = lin & 31;
                int gr = rowBase + s * 32 + rl;
                int ok = (gr < N_NODES);
                int grc = ok ? gr : 0;
                cp_async16(base + lin * 16, X + (size_t)grc * 128 + kq * 4, ok ? 16 : 0);
            }
            CP_COMMIT();
        }

        #pragma unroll 1
        for (int slab = 0; slab < 4; slab++) {
            int buf = slab & 1;
            cp_wait<1>();
            __syncthreads();

            #pragma unroll
            for (int i = 0; i < 4; i++) {
                int lin = tid + 256 * i;
                float4 v = *(const float4*)&sRaw[buf][lin * 4];
                int base = sAddr[i];
                float hx = bf16_round(v.x), hy = bf16_round(v.y);
                float hz = bf16_round(v.z), hw = bf16_round(v.w);
                sHi[base]     = pack_bf16(hx, hy);
                sHi[base + 4] = pack_bf16(hz, hw);
                sLo[base]     = pack_bf16(v.x - hx, v.y - hy);
                sLo[base + 4] = pack_bf16(v.z - hz, v.w - hw);
            }
            __syncthreads();

            if (slab < 2) {
                uint32_t base = buf ? rawAddr1 : rawAddr0;
                #pragma unroll
                for (int i = 0; i < 4; i++) {
                    int lin = tid + 256 * i;
                    int rl = lin >> 5, kq = lin & 31;
                    int gr = rowBase + (slab + 2) * 32 + rl;
                    int ok = (gr < N_NODES);
                    int grc = ok ? gr : 0;
                    cp_async16(base + lin * 16, X + (size_t)grc * 128 + kq * 4, ok ? 16 : 0);
                }
            }
            CP_COMMIT();

            #pragma unroll 1
            for (int mb = 0; mb < 2; mb++) {
                float a0[2][4], a1[2][4], a2[2][4];
                #pragma unroll
                for (int nb = 0; nb < 2; nb++)
                    #pragma unroll
                    for (int j = 0; j < 4; j++) { a0[nb][j] = 0.f; a1[nb][j] = 0.f; a2[nb][j] = 0.f; }

                #pragma unroll
                for (int ks = 0; ks < 8; ks++) {
                    int idx = (mb * 8 + ks) * 128 + (lane ^ (ks << 2)) * 4;
                    uint4 ah = *(const uint4*)&sHi[idx];
                    uint4 al = *(const uint4*)&sLo[idx];
                    #pragma unroll
                    for (int nb = 0; nb < 2; nb++) {
                        mma_bf16(a0[nb], ah.x, ah.y, ah.z, ah.w, Whi[ks][nb][0], Whi[ks][nb][1]);
                        mma_bf16(a1[nb], al.x, al.y, al.z, al.w, Whi[ks][nb][0], Whi[ks][nb][1]);
                        mma_bf16(a2[nb], ah.x, ah.y, ah.z, ah.w, Wlo[ks][nb][0], Wlo[ks][nb][1]);
                    }
                }

                int r0 = rowBase + slab * 32 + mb * 16 + (lane >> 2);
                int r1 = r0 + 8;
                float d0 = (r0 < N_NODES) ? g_dinv[r0] : 0.f;
                float d1 = (r1 < N_NODES) ? g_dinv[r1] : 0.f;
                #pragma unroll
                for (int nb = 0; nb < 2; nb++) {
                    int cc = nbase + nb * 8 + (lane & 3) * 2;
                    float s0 = a0[nb][0] + a1[nb][0] + a2[nb][0];
                    float s1 = a0[nb][1] + a1[nb][1] + a2[nb][1];
                    float s2 = a0[nb][2] + a1[nb][2] + a2[nb][2];
                    float s3 = a0[nb][3] + a1[nb][3] + a2[nb][3];
                    if (r0 < N_NODES)
                        H[(size_t)r0 * 64 + (cc >> 1)] = __floats2half2_rn(s0 * d0, s1 * d0);
                    if (r1 < N_NODES)
                        H[(size_t)r1 * 64 + (cc >> 1)] = __floats2half2_rn(s2 * d1, s3 * d1);
                }
            }
        }
        __syncthreads();
    }
}

// ---------------- aggregation: 2 edges per LDG.128, shfl combine -------------
// out[c] = dinv[c]*(xts16[c] + sum_in xts16[s]) + bias
__global__ void __launch_bounds__(256) k_agg(const float* __restrict__ bias,
                                             float* __restrict__ outExt,
                                             int useExtOut) {
    int gw = (blockIdx.x * blockDim.x + threadIdx.x) >> 5;
    int lane = threadIdx.x & 31;
    if (gw >= N_NODES) return;
    int c = gw;
    int sub = lane >> 4;
    int ln  = lane & 15;

    const uint4* hv4 = (const uint4*)g_h16;
    float*       out = useExtOut ? outExt : g_buf1;

    float acc[8];
    #pragma unroll
    for (int j = 0; j < 8; j++) acc[j] = 0.f;

    if (sub == 0) acc8(acc, hv4[(size_t)c * 16 + ln]);   // self term

    int e0 = g_off[c];
    int e1 = e0 + g_deg[c];
    int e = e0;

    for (; e + 8 <= e1; e += 8) {
        int s0 = __ldg(&g_src[e     + sub]);
        int s1 = __ldg(&g_src[e + 2 + sub]);
        int s2 = __ldg(&g_src[e + 4 + sub]);
        int s3 = __ldg(&g_src[e + 6 + sub]);
        uint4 u0 = hv4[(size_t)s0 * 16 + ln];
        uint4 u1 = hv4[(size_t)s1 * 16 + ln];
        uint4 u2 = hv4[(size_t)s2 * 16 + ln];
        uint4 u3 = hv4[(size_t)s3 * 16 + ln];
        acc8(acc, u0); acc8(acc, u1); acc8(acc, u2); acc8(acc, u3);
    }
    for (; e < e1; e += 2) {
        int idx = e + sub;
        if (idx < e1) {
            int s = __ldg(&g_src[idx]);
            acc8(acc, hv4[(size_t)s * 16 + ln]);
        }
    }

    float res[8];
    #pragma unroll
    for (int j = 0; j < 8; j++)
        res[j] = acc[j] + __shfl_xor_sync(0xFFFFFFFFu, acc[j], 16);

    float dc = g_dinv[c];
    int o0 = sub * 4;
    int fslot = ln * 2 + sub;
    float4 b = ((const float4*)bias)[fslot];
    float4 o = make_float4(res[o0 + 0] * dc + b.x, res[o0 + 1] * dc + b.y,
                           res[o0 + 2] * dc + b.z, res[o0 + 3] * dc + b.w);
    ((float4*)out)[(size_t)c * 32 + fslot] = o;
}

// ---------------- launch: fork fill ∥ mgemm1 in the captured graph -----------
extern "C" void kernel_launch(void* const* d_in, const int* in_sizes, int n_in,
                              void* d_out, int out_size) {
    const float* X  = (const float*)d_in[0];
    const void*  EI = d_in[1];
    const float* W1 = (const float*)d_in[2];
    const float* B1 = (const float*)d_in[3];
    const float* W2 = (const float*)d_in[4];
    const float* B2 = (const float*)d_in[5];
    float*       out = (float*)d_out;

    // Created once, on the (uncaptured) correctness call; reused thereafter.
    // Identical launch sequence every call -> deterministic work.
    static cudaStream_t s1 = nullptr;
    static cudaEvent_t  evFork = nullptr, evJoin = nullptr;
    if (s1 == nullptr) {
        cudaStreamCreateWithFlags(&s1, cudaStreamNonBlocking);
        cudaEventCreateWithFlags(&evFork, cudaEventDisableTiming);
        cudaEventCreateWithFlags(&evJoin, cudaEventDisableTiming);
    }

    const int edgeBlocks = (N_EDGES + 255) / 256;
    const int aggBlocks  = (N_NODES * 32 + 255) / 256;

    k_init<<<NBLK, 256>>>((const int*)EI);
    k_count<<<edgeBlocks, 256>>>(EI);
    k_offa<<<NBLK, 256>>>();

    // fork: mgemm1 on s1, fill stays on the capture stream
    cudaEventRecord(evFork, 0);
    cudaStreamWaitEvent(s1, evFork, 0);
    k_mgemm<<<GEMM_GRID, 256, 0, s1>>>(X, W1, /*src=*/0);
    cudaEventRecord(evJoin, s1);

    k_fill<<<edgeBlocks, 256>>>(EI);

    // join
    cudaStreamWaitEvent(0, evJoin, 0);

    k_agg<<<aggBlocks, 256>>>(B1, out, 0);               // h -> buf1
    k_mgemm<<<GEMM_GRID, 256>>>(nullptr, W2, /*src=*/1); // xts -> g_h16
    k_agg<<<aggBlocks, 256>>>(B2, out, 1);               // -> d_out
}